// round 2
// baseline (speedup 1.0000x reference)
#include <cuda_runtime.h>
#include <cuda_bf16.h>
#include <cstdint>
#include <cstddef>

// ---------------------------------------------------------------------------
// CrossLayerLateral: out = x_current + alpha * (x_prev @ W^T), W from COO.
// sm_100 (non-'a') target: no tcgen05/TMA. Use classic cp.async + ldmatrix +
// mma.sync.m16n8k16 bf16 pipeline. Densify W (fp32 atomics) -> bf16, convert
// x_prev -> bf16, 128x256x32 tiles, 3-stage pipeline, fused axpy epilogue.
// ---------------------------------------------------------------------------

#define HID 2048
#define MROWS_MAX 8192
#define BM 128
#define BN 256
#define BK 32
#define STAGES 3
#define NKT (HID / BK)          // 64
#define ROWPAD 40               // BK + 8 pad elems (80B row stride, ldmatrix conflict-free)

// A stage: 128 rows * 40 * 2B = 10240 B ; B stage: 256 * 40 * 2 = 20480 B
#define A_STAGE_BYTES (BM * ROWPAD * 2)
#define B_STAGE_BYTES (BN * ROWPAD * 2)
#define SMEM_BYTES (STAGES * (A_STAGE_BYTES + B_STAGE_BYTES))   // 92160

// -------------------- device scratch (static: no allocs) -------------------
__device__ float         g_Wf[HID * HID];          // 16 MB fp32 dense W
__device__ __nv_bfloat16 g_Wb[HID * HID];          // 8 MB  bf16 W  [i][j] (N-major rows, K contiguous)
__device__ __nv_bfloat16 g_Xb[MROWS_MAX * HID];    // 32 MB bf16 x_prev

// -------------------- preprocessing ----------------------------------------
__global__ void zero_w_kernel() {
    float4* p = reinterpret_cast<float4*>(g_Wf);
    for (int i = blockIdx.x * blockDim.x + threadIdx.x; i < HID * HID / 4;
         i += gridDim.x * blockDim.x)
        p[i] = make_float4(0.f, 0.f, 0.f, 0.f);
}

__global__ void scatter_kernel(const int* __restrict__ idx,
                               const float* __restrict__ val, int nnz) {
    int k = blockIdx.x * blockDim.x + threadIdx.x;
    if (k < nnz) {
        int i = idx[k];
        int j = idx[nnz + k];
        atomicAdd(&g_Wf[(size_t)i * HID + j], val[k]);
    }
}

__global__ void conv_w_kernel() {
    int i = blockIdx.x * blockDim.x + threadIdx.x;
    if (i < HID * HID / 4) {
        float4 v = reinterpret_cast<const float4*>(g_Wf)[i];
        __nv_bfloat162* d = reinterpret_cast<__nv_bfloat162*>(g_Wb);
        d[2 * i]     = __float22bfloat162_rn(make_float2(v.x, v.y));
        d[2 * i + 1] = __float22bfloat162_rn(make_float2(v.z, v.w));
    }
}

__global__ void conv_x_kernel(const float* __restrict__ src, int n4) {
    int i = blockIdx.x * blockDim.x + threadIdx.x;
    if (i < n4) {
        float4 v = reinterpret_cast<const float4*>(src)[i];
        __nv_bfloat162* d = reinterpret_cast<__nv_bfloat162*>(g_Xb);
        d[2 * i]     = __float22bfloat162_rn(make_float2(v.x, v.y));
        d[2 * i + 1] = __float22bfloat162_rn(make_float2(v.z, v.w));
    }
}

// -------------------- GEMM helpers ------------------------------------------
__device__ __forceinline__ void cp_async16(uint32_t dst, const void* src) {
    asm volatile("cp.async.cg.shared.global [%0], [%1], 16;" :: "r"(dst), "l"(src));
}
__device__ __forceinline__ void cp_commit() {
    asm volatile("cp.async.commit_group;" ::: "memory");
}
template <int N>
__device__ __forceinline__ void cp_wait() {
    asm volatile("cp.async.wait_group %0;" :: "n"(N) : "memory");
}

__device__ __forceinline__ void ldsm_x4(uint32_t& r0, uint32_t& r1, uint32_t& r2,
                                        uint32_t& r3, uint32_t addr) {
    asm volatile("ldmatrix.sync.aligned.m8n8.x4.shared.b16 {%0,%1,%2,%3}, [%4];"
                 : "=r"(r0), "=r"(r1), "=r"(r2), "=r"(r3) : "r"(addr));
}

__device__ __forceinline__ void mma16816(float& c0, float& c1, float& c2, float& c3,
                                         uint32_t a0, uint32_t a1, uint32_t a2, uint32_t a3,
                                         uint32_t b0, uint32_t b1) {
    asm volatile(
        "mma.sync.aligned.m16n8k16.row.col.f32.bf16.bf16.f32 "
        "{%0,%1,%2,%3}, {%4,%5,%6,%7}, {%8,%9}, {%0,%1,%2,%3};"
        : "+f"(c0), "+f"(c1), "+f"(c2), "+f"(c3)
        : "r"(a0), "r"(a1), "r"(a2), "r"(a3), "r"(b0), "r"(b1));
}

// Load one K-chunk (stage) via cp.async: A 128x32 + B 256x32 bf16.
__device__ __forceinline__ void load_stage(uint32_t smA, uint32_t smB,
                                           int kt, int m0, int n0, int tid) {
    const int k0 = kt * BK;
#pragma unroll
    for (int i = 0; i < 6; i++) {
        int t = tid + i * 256;       // 0..1535 ; A: [0,512), B: [512,1536)
        bool isB = t >= 512;
        int u = isB ? t - 512 : t;
        int row = u >> 2;
        int c = u & 3;               // 16B chunk within row
        const __nv_bfloat16* g = isB
            ? g_Wb + (size_t)(n0 + row) * HID + k0 + c * 8
            : g_Xb + (size_t)(m0 + row) * HID + k0 + c * 8;
        uint32_t dst = (isB ? smB : smA) + (uint32_t)(row * ROWPAD + c * 8) * 2;
        cp_async16(dst, g);
    }
    cp_commit();
}

// -------------------- GEMM kernel -------------------------------------------
__global__ __launch_bounds__(256, 1)
void gemm_kernel(const float* __restrict__ x_cur,
                 const float* __restrict__ alpha_p,
                 float* __restrict__ out) {
    extern __shared__ char smraw[];
    const int tid  = threadIdx.x;
    const int wid  = tid >> 5;
    const int lane = tid & 31;
    const int n0 = blockIdx.x * BN;
    const int m0 = blockIdx.y * BM;
    const int wm = wid & 1;          // 2 warps along M
    const int wn = wid >> 1;         // 4 warps along N
    const int rm = wm * 64;          // warp tile 64x64
    const int rn = wn * 64;

    uint32_t smem;
    asm("{ .reg .u64 t; cvta.to.shared.u64 t, %1; cvt.u32.u64 %0, t; }"
        : "=r"(smem) : "l"(smraw));
    uint32_t smA[STAGES], smB[STAGES];
#pragma unroll
    for (int s = 0; s < STAGES; s++) {
        smA[s] = smem + s * A_STAGE_BYTES;
        smB[s] = smem + STAGES * A_STAGE_BYTES + s * B_STAGE_BYTES;
    }

    float acc[4][8][4];
#pragma unroll
    for (int mf = 0; mf < 4; mf++)
#pragma unroll
        for (int nf = 0; nf < 8; nf++)
#pragma unroll
            for (int q = 0; q < 4; q++) acc[mf][nf][q] = 0.f;

    // prologue: stages 0,1
    load_stage(smA[0], smB[0], 0, m0, n0, tid);
    load_stage(smA[1], smB[1], 1, m0, n0, tid);
    cp_wait<1>();
    __syncthreads();

    // ldmatrix base addresses for this lane
    const int ldrowA = rm + (lane & 15);
    const int ldrowB = rn + (lane & 15);
    const int ldcol  = (lane >> 4) * 8;     // elems

    for (int kt = 0; kt < NKT; kt++) {
        const int s = kt % STAGES;
        if (kt + 2 < NKT) {
            load_stage(smA[(kt + 2) % STAGES], smB[(kt + 2) % STAGES],
                       kt + 2, m0, n0, tid);
        }

#pragma unroll
        for (int ks = 0; ks < 2; ks++) {    // two k16 steps in BK=32
            uint32_t a[4][4], b[4][4];
#pragma unroll
            for (int mf = 0; mf < 4; mf++) {
                uint32_t addr = smA[s] +
                    (uint32_t)((ldrowA + mf * 16) * ROWPAD + ks * 16 + ldcol) * 2;
                ldsm_x4(a[mf][0], a[mf][1], a[mf][2], a[mf][3], addr);
            }
#pragma unroll
            for (int bf = 0; bf < 4; bf++) {  // each covers n16 = two n8 frags
                uint32_t addr = smB[s] +
                    (uint32_t)((ldrowB + bf * 16) * ROWPAD + ks * 16 + ldcol) * 2;
                ldsm_x4(b[bf][0], b[bf][1], b[bf][2], b[bf][3], addr);
            }
#pragma unroll
            for (int mf = 0; mf < 4; mf++)
#pragma unroll
                for (int bf = 0; bf < 4; bf++) {
                    mma16816(acc[mf][2 * bf][0], acc[mf][2 * bf][1],
                             acc[mf][2 * bf][2], acc[mf][2 * bf][3],
                             a[mf][0], a[mf][1], a[mf][2], a[mf][3],
                             b[bf][0], b[bf][2]);
                    mma16816(acc[mf][2 * bf + 1][0], acc[mf][2 * bf + 1][1],
                             acc[mf][2 * bf + 1][2], acc[mf][2 * bf + 1][3],
                             a[mf][0], a[mf][1], a[mf][2], a[mf][3],
                             b[bf][1], b[bf][3]);
                }
        }

        if (kt + 2 < NKT) cp_wait<1>(); else cp_wait<0>();
        __syncthreads();
    }

    // -------------------- fused epilogue: out = x_cur + alpha*acc ----------
    const float alpha = __ldg(alpha_p);
#pragma unroll
    for (int mf = 0; mf < 4; mf++) {
        const int r = m0 + rm + mf * 16 + (lane >> 2);
#pragma unroll
        for (int nf = 0; nf < 8; nf++) {
            const int cidx = n0 + rn + nf * 8 + (lane & 3) * 2;
            size_t g0 = (size_t)r * HID + cidx;
            float2 x0 = *reinterpret_cast<const float2*>(x_cur + g0);
            float2 o0;
            o0.x = fmaf(alpha, acc[mf][nf][0], x0.x);
            o0.y = fmaf(alpha, acc[mf][nf][1], x0.y);
            *reinterpret_cast<float2*>(out + g0) = o0;
            size_t g1 = g0 + (size_t)8 * HID;
            float2 x1 = *reinterpret_cast<const float2*>(x_cur + g1);
            float2 o1;
            o1.x = fmaf(alpha, acc[mf][nf][2], x1.x);
            o1.y = fmaf(alpha, acc[mf][nf][3], x1.y);
            *reinterpret_cast<float2*>(out + g1) = o1;
        }
    }
}

// -------------------- launcher ---------------------------------------------
extern "C" void kernel_launch(void* const* d_in, const int* in_sizes, int n_in,
                              void* d_out, int out_size) {
    const float* x_cur  = (const float*)d_in[0];
    const float* x_prev = (const float*)d_in[1];
    const float* alpha  = (const float*)d_in[2];
    const float* vals   = (const float*)d_in[3];
    const int*   idx    = (const int*)d_in[4];
    const int nnz   = in_sizes[3];
    const int mrows = in_sizes[0] / HID;     // 8192

    cudaFuncSetAttribute(gemm_kernel,
                         cudaFuncAttributeMaxDynamicSharedMemorySize, SMEM_BYTES);

    zero_w_kernel<<<2048, 256>>>();
    scatter_kernel<<<(nnz + 255) / 256, 256>>>(idx, vals, nnz);
    conv_w_kernel<<<(HID * HID / 4 + 255) / 256, 256>>>();
    const int n4x = mrows * HID / 4;
    conv_x_kernel<<<(n4x + 255) / 256, 256>>>(x_prev, n4x);

    dim3 grid(HID / BN, mrows / BM);         // 8 x 64 = 512 CTAs
    gemm_kernel<<<grid, 256, SMEM_BYTES>>>(x_cur, alpha, (float*)d_out);
}

// round 3
// speedup vs baseline: 1.2633x; 1.2633x over previous
#include <cuda_runtime.h>
#include <cuda_bf16.h>
#include <cstdint>
#include <cstddef>

// ---------------------------------------------------------------------------
// CrossLayerLateral: out = x_current + alpha * (x_prev @ W^T), W from COO.
// compute_100 target (no tcgen05/TMA): cp.async + ldmatrix + FP8 e4m3
// mma.sync.m16n8k32 (2x MACs/instr vs bf16 k16; kernel was HMMA-issue-bound).
// W scaled by 512 into e4m3 range; alpha/512 in epilogue.
// ---------------------------------------------------------------------------

#define HID 2048
#define MROWS_MAX 8192
#define BM 128
#define BN 256
#define BK 64                   // fp8 elements (bytes) per K-chunk
#define STAGES 3
#define NKT (HID / BK)          // 32
#define ROWPAD 80               // bytes per smem row (64 + 16 pad): ldsm conflict-free
#define WSCALE 512.0f

#define A_STAGE_BYTES (BM * ROWPAD)     // 10240
#define B_STAGE_BYTES (BN * ROWPAD)     // 20480
#define SMEM_BYTES (STAGES * (A_STAGE_BYTES + B_STAGE_BYTES))   // 92160

// -------------------- device scratch (static: no allocs) -------------------
__device__ float   g_Wf[HID * HID];            // 16 MB fp32 dense W
__device__ uint8_t g_Wq[HID * HID];            // 4 MB e4m3 W*512  [i][j], j contiguous
__device__ uint8_t g_Xq[MROWS_MAX * HID];      // 16 MB e4m3 x_prev

// -------------------- preprocessing ----------------------------------------
__global__ void zero_w_kernel() {
    float4* p = reinterpret_cast<float4*>(g_Wf);
    for (int i = blockIdx.x * blockDim.x + threadIdx.x; i < HID * HID / 4;
         i += gridDim.x * blockDim.x)
        p[i] = make_float4(0.f, 0.f, 0.f, 0.f);
}

__global__ void scatter_kernel(const int* __restrict__ idx,
                               const float* __restrict__ val, int nnz) {
    int k = blockIdx.x * blockDim.x + threadIdx.x;
    if (k < nnz) {
        int i = idx[k];
        int j = idx[nnz + k];
        atomicAdd(&g_Wf[(size_t)i * HID + j], val[k]);
    }
}

__device__ __forceinline__ uint16_t f2_to_e4m3x2(float lo, float hi) {
    uint16_t p;
    asm("cvt.rn.satfinite.e4m3x2.f32 %0, %1, %2;" : "=h"(p) : "f"(hi), "f"(lo));
    return p;
}

__global__ void conv_w_kernel() {
    int i = blockIdx.x * blockDim.x + threadIdx.x;   // one float4 -> 4 bytes
    if (i < HID * HID / 4) {
        float4 v = reinterpret_cast<const float4*>(g_Wf)[i];
        uint16_t p0 = f2_to_e4m3x2(v.x * WSCALE, v.y * WSCALE);
        uint16_t p1 = f2_to_e4m3x2(v.z * WSCALE, v.w * WSCALE);
        reinterpret_cast<uint32_t*>(g_Wq)[i] = (uint32_t)p0 | ((uint32_t)p1 << 16);
    }
}

__global__ void conv_x_kernel(const float* __restrict__ src, int n4) {
    int i = blockIdx.x * blockDim.x + threadIdx.x;
    if (i < n4) {
        float4 v = reinterpret_cast<const float4*>(src)[i];
        uint16_t p0 = f2_to_e4m3x2(v.x, v.y);
        uint16_t p1 = f2_to_e4m3x2(v.z, v.w);
        reinterpret_cast<uint32_t*>(g_Xq)[i] = (uint32_t)p0 | ((uint32_t)p1 << 16);
    }
}

// -------------------- GEMM helpers ------------------------------------------
__device__ __forceinline__ void cp_async16(uint32_t dst, const void* src) {
    asm volatile("cp.async.cg.shared.global [%0], [%1], 16;" :: "r"(dst), "l"(src));
}
__device__ __forceinline__ void cp_commit() {
    asm volatile("cp.async.commit_group;" ::: "memory");
}
template <int N>
__device__ __forceinline__ void cp_wait() {
    asm volatile("cp.async.wait_group %0;" :: "n"(N) : "memory");
}

__device__ __forceinline__ void ldsm_x4(uint32_t& r0, uint32_t& r1, uint32_t& r2,
                                        uint32_t& r3, uint32_t addr) {
    asm volatile("ldmatrix.sync.aligned.m8n8.x4.shared.b16 {%0,%1,%2,%3}, [%4];"
                 : "=r"(r0), "=r"(r1), "=r"(r2), "=r"(r3) : "r"(addr));
}

// FP8 e4m3 MMA, K=32. Fragment layout is byte-pair-isomorphic to bf16 k16,
// so ldmatrix.b16 fragments feed it directly.
__device__ __forceinline__ void mma_fp8(float& c0, float& c1, float& c2, float& c3,
                                        uint32_t a0, uint32_t a1, uint32_t a2, uint32_t a3,
                                        uint32_t b0, uint32_t b1) {
    asm volatile(
        "mma.sync.aligned.m16n8k32.row.col.f32.e4m3.e4m3.f32 "
        "{%0,%1,%2,%3}, {%4,%5,%6,%7}, {%8,%9}, {%0,%1,%2,%3};"
        : "+f"(c0), "+f"(c1), "+f"(c2), "+f"(c3)
        : "r"(a0), "r"(a1), "r"(a2), "r"(a3), "r"(b0), "r"(b1));
}

// Load one K-chunk (stage): A 128x64B + B 256x64B via 16B cp.async.
__device__ __forceinline__ void load_stage(uint32_t smA, uint32_t smB,
                                           int kt, int m0, int n0, int tid) {
    const int k0 = kt * BK;
#pragma unroll
    for (int i = 0; i < 6; i++) {
        int t = tid + i * 256;         // 0..1535 ; A: [0,512), B: [512,1536)
        bool isB = t >= 512;
        int u = isB ? t - 512 : t;
        int row = u >> 2;
        int c = u & 3;                 // 16B chunk within 64B row
        const uint8_t* g = isB
            ? g_Wq + (size_t)(n0 + row) * HID + k0 + c * 16
            : g_Xq + (size_t)(m0 + row) * HID + k0 + c * 16;
        uint32_t dst = (isB ? smB : smA) + (uint32_t)(row * ROWPAD + c * 16);
        cp_async16(dst, g);
    }
    cp_commit();
}

// -------------------- GEMM kernel -------------------------------------------
__global__ __launch_bounds__(256, 1)
void gemm_kernel(const float* __restrict__ x_cur,
                 const float* __restrict__ alpha_p,
                 float* __restrict__ out) {
    extern __shared__ char smraw[];
    const int tid  = threadIdx.x;
    const int wid  = tid >> 5;
    const int lane = tid & 31;
    const int n0 = blockIdx.x * BN;
    const int m0 = blockIdx.y * BM;
    const int wm = wid & 1;            // 2 warps along M
    const int wn = wid >> 1;           // 4 warps along N
    const int rm = wm * 64;            // warp tile 64x64
    const int rn = wn * 64;

    uint32_t smem;
    asm("{ .reg .u64 t; cvta.to.shared.u64 t, %1; cvt.u32.u64 %0, t; }"
        : "=r"(smem) : "l"(smraw));
    uint32_t smA[STAGES], smB[STAGES];
#pragma unroll
    for (int s = 0; s < STAGES; s++) {
        smA[s] = smem + s * A_STAGE_BYTES;
        smB[s] = smem + STAGES * A_STAGE_BYTES + s * B_STAGE_BYTES;
    }

    float acc[4][8][4];
#pragma unroll
    for (int mf = 0; mf < 4; mf++)
#pragma unroll
        for (int nf = 0; nf < 8; nf++)
#pragma unroll
            for (int q = 0; q < 4; q++) acc[mf][nf][q] = 0.f;

    load_stage(smA[0], smB[0], 0, m0, n0, tid);
    load_stage(smA[1], smB[1], 1, m0, n0, tid);
    cp_wait<1>();
    __syncthreads();

    // ldmatrix lane addressing (byte units): 16 rows x 32B region per x4
    const int ldrowA = rm + (lane & 15);
    const int ldrowB = rn + (lane & 15);
    const int ldcol  = (lane >> 4) * 16;    // byte offset within 32B

    for (int kt = 0; kt < NKT; kt++) {
        const int s = kt % STAGES;
        if (kt + 2 < NKT)
            load_stage(smA[(kt + 2) % STAGES], smB[(kt + 2) % STAGES],
                       kt + 2, m0, n0, tid);

#pragma unroll
        for (int ks = 0; ks < 2; ks++) {    // two k32 steps in BK=64
            uint32_t a[4][4], b[4][4];
#pragma unroll
            for (int mf = 0; mf < 4; mf++) {
                uint32_t addr = smA[s] +
                    (uint32_t)((ldrowA + mf * 16) * ROWPAD + ks * 32 + ldcol);
                ldsm_x4(a[mf][0], a[mf][1], a[mf][2], a[mf][3], addr);
            }
#pragma unroll
            for (int bf = 0; bf < 4; bf++) {
                uint32_t addr = smB[s] +
                    (uint32_t)((ldrowB + bf * 16) * ROWPAD + ks * 32 + ldcol);
                ldsm_x4(b[bf][0], b[bf][1], b[bf][2], b[bf][3], addr);
            }
#pragma unroll
            for (int mf = 0; mf < 4; mf++)
#pragma unroll
                for (int bf = 0; bf < 4; bf++) {
                    mma_fp8(acc[mf][2 * bf][0], acc[mf][2 * bf][1],
                            acc[mf][2 * bf][2], acc[mf][2 * bf][3],
                            a[mf][0], a[mf][1], a[mf][2], a[mf][3],
                            b[bf][0], b[bf][2]);
                    mma_fp8(acc[mf][2 * bf + 1][0], acc[mf][2 * bf + 1][1],
                            acc[mf][2 * bf + 1][2], acc[mf][2 * bf + 1][3],
                            a[mf][0], a[mf][1], a[mf][2], a[mf][3],
                            b[bf][1], b[bf][3]);
                }
        }

        if (kt + 2 < NKT) cp_wait<1>(); else cp_wait<0>();
        __syncthreads();
    }

    // -------------------- fused epilogue: out = x_cur + (alpha/512)*acc ----
    const float alpha = __ldg(alpha_p) * (1.0f / WSCALE);
#pragma unroll
    for (int mf = 0; mf < 4; mf++) {
        const int r = m0 + rm + mf * 16 + (lane >> 2);
#pragma unroll
        for (int nf = 0; nf < 8; nf++) {
            const int cidx = n0 + rn + nf * 8 + (lane & 3) * 2;
            size_t g0 = (size_t)r * HID + cidx;
            float2 x0 = *reinterpret_cast<const float2*>(x_cur + g0);
            float2 o0;
            o0.x = fmaf(alpha, acc[mf][nf][0], x0.x);
            o0.y = fmaf(alpha, acc[mf][nf][1], x0.y);
            *reinterpret_cast<float2*>(out + g0) = o0;
            size_t g1 = g0 + (size_t)8 * HID;
            float2 x1 = *reinterpret_cast<const float2*>(x_cur + g1);
            float2 o1;
            o1.x = fmaf(alpha, acc[mf][nf][2], x1.x);
            o1.y = fmaf(alpha, acc[mf][nf][3], x1.y);
            *reinterpret_cast<float2*>(out + g1) = o1;
        }
    }
}

// -------------------- launcher ---------------------------------------------
extern "C" void kernel_launch(void* const* d_in, const int* in_sizes, int n_in,
                              void* d_out, int out_size) {
    const float* x_cur  = (const float*)d_in[0];
    const float* x_prev = (const float*)d_in[1];
    const float* alpha  = (const float*)d_in[2];
    const float* vals   = (const float*)d_in[3];
    const int*   idx    = (const int*)d_in[4];
    const int nnz   = in_sizes[3];
    const int mrows = in_sizes[0] / HID;     // 8192

    cudaFuncSetAttribute(gemm_kernel,
                         cudaFuncAttributeMaxDynamicSharedMemorySize, SMEM_BYTES);

    zero_w_kernel<<<2048, 256>>>();
    scatter_kernel<<<(nnz + 255) / 256, 256>>>(idx, vals, nnz);
    conv_w_kernel<<<(HID * HID / 4 + 255) / 256, 256>>>();
    const int n4x = mrows * HID / 4;
    conv_x_kernel<<<(n4x + 255) / 256, 256>>>(x_prev, n4x);

    dim3 grid(HID / BN, mrows / BM);         // 8 x 64 = 512 CTAs
    gemm_kernel<<<grid, 256, SMEM_BYTES>>>(x_cur, alpha, (float*)d_out);
}

// round 4
// speedup vs baseline: 1.2808x; 1.0139x over previous
#include <cuda_runtime.h>
#include <cuda_bf16.h>
#include <cuda_fp16.h>
#include <cstdint>
#include <cstddef>

// ---------------------------------------------------------------------------
// CrossLayerLateral: out = x_current + alpha * (x_prev @ W^T), W from COO.
// compute_100 (no tcgen05/TMA): cp.async + ldmatrix + FP8 e4m3 mma.sync
// m16n8k32 with F16 accumulators (2x legacy-pipe rate hypothesis),
// 512 threads/CTA (4 warps/SMSP), 4-stage pipeline.
// W scaled by 512 into e4m3 range; alpha/512 in epilogue.
// ---------------------------------------------------------------------------

#define HID 2048
#define MROWS_MAX 8192
#define BM 128
#define BN 256
#define BK 64                   // fp8 bytes per K-chunk
#define STAGES 4
#define NKT (HID / BK)          // 32
#define ROWPAD 80               // bytes per smem row (64 + 16 pad)
#define WSCALE 512.0f
#define NTHREADS 512

#define A_STAGE_BYTES (BM * ROWPAD)     // 10240
#define B_STAGE_BYTES (BN * ROWPAD)     // 20480
#define SMEM_BYTES (STAGES * (A_STAGE_BYTES + B_STAGE_BYTES))   // 122880

// -------------------- device scratch (static: no allocs) -------------------
__device__ float   g_Wf[HID * HID];            // 16 MB fp32 dense W
__device__ uint8_t g_Wq[HID * HID];            // 4 MB e4m3 W*512, [i][j] j contig
__device__ uint8_t g_Xq[MROWS_MAX * HID];      // 16 MB e4m3 x_prev

// -------------------- preprocessing ----------------------------------------
__global__ void zero_w_kernel() {
    float4* p = reinterpret_cast<float4*>(g_Wf);
    for (int i = blockIdx.x * blockDim.x + threadIdx.x; i < HID * HID / 4;
         i += gridDim.x * blockDim.x)
        p[i] = make_float4(0.f, 0.f, 0.f, 0.f);
}

__global__ void scatter_kernel(const int* __restrict__ idx,
                               const float* __restrict__ val, int nnz) {
    int k = blockIdx.x * blockDim.x + threadIdx.x;
    if (k < nnz) {
        int i = idx[k];
        int j = idx[nnz + k];
        atomicAdd(&g_Wf[(size_t)i * HID + j], val[k]);
    }
}

__device__ __forceinline__ uint16_t f2_to_e4m3x2(float lo, float hi) {
    uint16_t p;
    asm("cvt.rn.satfinite.e4m3x2.f32 %0, %1, %2;" : "=h"(p) : "f"(hi), "f"(lo));
    return p;
}

__global__ void conv_w_kernel() {
    int i = blockIdx.x * blockDim.x + threadIdx.x;   // one float4 -> 4 bytes
    if (i < HID * HID / 4) {
        float4 v = reinterpret_cast<const float4*>(g_Wf)[i];
        uint16_t p0 = f2_to_e4m3x2(v.x * WSCALE, v.y * WSCALE);
        uint16_t p1 = f2_to_e4m3x2(v.z * WSCALE, v.w * WSCALE);
        reinterpret_cast<uint32_t*>(g_Wq)[i] = (uint32_t)p0 | ((uint32_t)p1 << 16);
    }
}

__global__ void conv_x_kernel(const float* __restrict__ src, int n8) {
    int i = blockIdx.x * blockDim.x + threadIdx.x;   // two float4 -> 8 bytes
    if (i < n8) {
        float4 v0 = reinterpret_cast<const float4*>(src)[2 * i];
        float4 v1 = reinterpret_cast<const float4*>(src)[2 * i + 1];
        uint32_t lo = (uint32_t)f2_to_e4m3x2(v0.x, v0.y) |
                      ((uint32_t)f2_to_e4m3x2(v0.z, v0.w) << 16);
        uint32_t hi = (uint32_t)f2_to_e4m3x2(v1.x, v1.y) |
                      ((uint32_t)f2_to_e4m3x2(v1.z, v1.w) << 16);
        reinterpret_cast<uint2*>(g_Xq)[i] = make_uint2(lo, hi);
    }
}

// -------------------- GEMM helpers ------------------------------------------
__device__ __forceinline__ void cp_async16(uint32_t dst, const void* src) {
    asm volatile("cp.async.cg.shared.global [%0], [%1], 16;" :: "r"(dst), "l"(src));
}
__device__ __forceinline__ void cp_commit() {
    asm volatile("cp.async.commit_group;" ::: "memory");
}
template <int N>
__device__ __forceinline__ void cp_wait() {
    asm volatile("cp.async.wait_group %0;" :: "n"(N) : "memory");
}

__device__ __forceinline__ void ldsm_x4(uint32_t& r0, uint32_t& r1, uint32_t& r2,
                                        uint32_t& r3, uint32_t addr) {
    asm volatile("ldmatrix.sync.aligned.m8n8.x4.shared.b16 {%0,%1,%2,%3}, [%4];"
                 : "=r"(r0), "=r"(r1), "=r"(r2), "=r"(r3) : "r"(addr));
}

// FP8 e4m3 MMA, K=32, F16 accumulate (packed 2xf16 per .b32).
__device__ __forceinline__ void mma_fp8_f16(uint32_t& c0, uint32_t& c1,
                                            uint32_t a0, uint32_t a1, uint32_t a2, uint32_t a3,
                                            uint32_t b0, uint32_t b1) {
    asm volatile(
        "mma.sync.aligned.m16n8k32.row.col.f16.e4m3.e4m3.f16 "
        "{%0,%1}, {%2,%3,%4,%5}, {%6,%7}, {%0,%1};"
        : "+r"(c0), "+r"(c1)
        : "r"(a0), "r"(a1), "r"(a2), "r"(a3), "r"(b0), "r"(b1));
}

// Load one K-chunk (stage): A 128x64B + B 256x64B via 16B cp.async.
// 1536 chunks over 512 threads = 3 per thread.
__device__ __forceinline__ void load_stage(uint32_t smA, uint32_t smB,
                                           int kt, int m0, int n0, int tid) {
    const int k0 = kt * BK;
#pragma unroll
    for (int i = 0; i < 3; i++) {
        int t = tid + i * NTHREADS;    // 0..1535 ; A: [0,512), B: [512,1536)
        bool isB = t >= 512;
        int u = isB ? t - 512 : t;
        int row = u >> 2;
        int c = u & 3;                 // 16B chunk within 64B row
        const uint8_t* g = isB
            ? g_Wq + (size_t)(n0 + row) * HID + k0 + c * 16
            : g_Xq + (size_t)(m0 + row) * HID + k0 + c * 16;
        uint32_t dst = (isB ? smB : smA) + (uint32_t)(row * ROWPAD + c * 16);
        cp_async16(dst, g);
    }
    cp_commit();
}

// -------------------- GEMM kernel -------------------------------------------
__global__ __launch_bounds__(NTHREADS, 1)
void gemm_kernel(const float* __restrict__ x_cur,
                 const float* __restrict__ alpha_p,
                 float* __restrict__ out) {
    extern __shared__ char smraw[];
    const int tid  = threadIdx.x;
    const int wid  = tid >> 5;
    const int lane = tid & 31;
    const int n0 = blockIdx.x * BN;
    const int m0 = blockIdx.y * BM;
    const int wm = wid & 3;            // 4 warps along M (32 rows each)
    const int wn = wid >> 2;           // 4 warps along N (64 cols each)
    const int rm = wm * 32;
    const int rn = wn * 64;

    uint32_t smem;
    asm("{ .reg .u64 t; cvta.to.shared.u64 t, %1; cvt.u32.u64 %0, t; }"
        : "=r"(smem) : "l"(smraw));
    uint32_t smA[STAGES], smB[STAGES];
#pragma unroll
    for (int s = 0; s < STAGES; s++) {
        smA[s] = smem + s * A_STAGE_BYTES;
        smB[s] = smem + STAGES * A_STAGE_BYTES + s * B_STAGE_BYTES;
    }

    // acc[mf][nf]: packed f16x2 pairs, zero-init
    uint32_t acc[2][8][2];
#pragma unroll
    for (int mf = 0; mf < 2; mf++)
#pragma unroll
        for (int nf = 0; nf < 8; nf++) {
            acc[mf][nf][0] = 0u; acc[mf][nf][1] = 0u;
        }

    load_stage(smA[0], smB[0], 0, m0, n0, tid);
    load_stage(smA[1], smB[1], 1, m0, n0, tid);
    load_stage(smA[2], smB[2], 2, m0, n0, tid);
    cp_wait<2>();
    __syncthreads();

    const int ldrowA = rm + (lane & 15);
    const int ldrowB = rn + (lane & 15);
    const int ldcol  = (lane >> 4) * 16;

    for (int kt = 0; kt < NKT; kt++) {
        const int s = kt & (STAGES - 1);
        if (kt + 3 < NKT)
            load_stage(smA[(kt + 3) & (STAGES - 1)], smB[(kt + 3) & (STAGES - 1)],
                       kt + 3, m0, n0, tid);

#pragma unroll
        for (int ks = 0; ks < 2; ks++) {     // two k32 steps in BK=64
            uint32_t a[2][4], b[4][4];
#pragma unroll
            for (int mf = 0; mf < 2; mf++) {
                uint32_t addr = smA[s] +
                    (uint32_t)((ldrowA + mf * 16) * ROWPAD + ks * 32 + ldcol);
                ldsm_x4(a[mf][0], a[mf][1], a[mf][2], a[mf][3], addr);
            }
#pragma unroll
            for (int bf = 0; bf < 4; bf++) {
                uint32_t addr = smB[s] +
                    (uint32_t)((ldrowB + bf * 16) * ROWPAD + ks * 32 + ldcol);
                ldsm_x4(b[bf][0], b[bf][1], b[bf][2], b[bf][3], addr);
            }
#pragma unroll
            for (int mf = 0; mf < 2; mf++)
#pragma unroll
                for (int bf = 0; bf < 4; bf++) {
                    mma_fp8_f16(acc[mf][2 * bf][0], acc[mf][2 * bf][1],
                                a[mf][0], a[mf][1], a[mf][2], a[mf][3],
                                b[bf][0], b[bf][2]);
                    mma_fp8_f16(acc[mf][2 * bf + 1][0], acc[mf][2 * bf + 1][1],
                                a[mf][0], a[mf][1], a[mf][2], a[mf][3],
                                b[bf][1], b[bf][3]);
                }
        }

        if (kt + 3 < NKT) cp_wait<2>(); else cp_wait<0>();
        __syncthreads();
    }

    // -------------------- fused epilogue: out = x_cur + (alpha/512)*acc ----
    const float alpha = __ldg(alpha_p) * (1.0f / WSCALE);
#pragma unroll
    for (int mf = 0; mf < 2; mf++) {
        const int r = m0 + rm + mf * 16 + (lane >> 2);
#pragma unroll
        for (int nf = 0; nf < 8; nf++) {
            const int cidx = n0 + rn + nf * 8 + (lane & 3) * 2;
            size_t g0 = (size_t)r * HID + cidx;
            float2 v0 = __half22float2(*reinterpret_cast<__half2*>(&acc[mf][nf][0]));
            float2 x0 = *reinterpret_cast<const float2*>(x_cur + g0);
            float2 o0;
            o0.x = fmaf(alpha, v0.x, x0.x);
            o0.y = fmaf(alpha, v0.y, x0.y);
            *reinterpret_cast<float2*>(out + g0) = o0;
            size_t g1 = g0 + (size_t)8 * HID;
            float2 v1 = __half22float2(*reinterpret_cast<__half2*>(&acc[mf][nf][1]));
            float2 x1 = *reinterpret_cast<const float2*>(x_cur + g1);
            float2 o1;
            o1.x = fmaf(alpha, v1.x, x1.x);
            o1.y = fmaf(alpha, v1.y, x1.y);
            *reinterpret_cast<float2*>(out + g1) = o1;
        }
    }
}

// -------------------- launcher ---------------------------------------------
extern "C" void kernel_launch(void* const* d_in, const int* in_sizes, int n_in,
                              void* d_out, int out_size) {
    const float* x_cur  = (const float*)d_in[0];
    const float* x_prev = (const float*)d_in[1];
    const float* alpha  = (const float*)d_in[2];
    const float* vals   = (const float*)d_in[3];
    const int*   idx    = (const int*)d_in[4];
    const int nnz   = in_sizes[3];
    const int mrows = in_sizes[0] / HID;     // 8192

    cudaFuncSetAttribute(gemm_kernel,
                         cudaFuncAttributeMaxDynamicSharedMemorySize, SMEM_BYTES);

    zero_w_kernel<<<2048, 256>>>();
    scatter_kernel<<<(nnz + 255) / 256, 256>>>(idx, vals, nnz);
    conv_w_kernel<<<(HID * HID / 4 + 255) / 256, 256>>>();
    const int n8x = mrows * HID / 8;
    conv_x_kernel<<<(n8x + 255) / 256, 256>>>(x_prev, n8x);

    dim3 grid(HID / BN, mrows / BM);         // 8 x 64 = 512 CTAs
    gemm_kernel<<<grid, NTHREADS, SMEM_BYTES>>>(x_cur, alpha, (float*)d_out);
}

// round 5
// speedup vs baseline: 1.6050x; 1.2531x over previous
#include <cuda_runtime.h>
#include <cuda_bf16.h>
#include <cuda_fp16.h>
#include <cstdint>
#include <cstddef>

// ---------------------------------------------------------------------------
// CrossLayerLateral: out = x_current + alpha * (x_prev @ W^T), W from COO.
// compute_100 (no tcgen05/TMA): cp.async + ldmatrix + FP8 e4m3 mma.sync
// m16n8k32, f16 accumulators. Legacy mma pipe is the roofline (~118
// MACs/cyc/SMSP); this round removes scheduling losses: 128x128 CTAs,
// 2 CTAs/SM co-resident (barrier-bubble overlap), 1024 CTAs (wave quant).
// ---------------------------------------------------------------------------

#define HID 2048
#define MROWS_MAX 8192
#define BM 128
#define BN 128
#define BK 64                   // fp8 bytes per K-chunk
#define STAGES 4
#define NKT (HID / BK)          // 32
#define ROWPAD 80               // bytes per smem row (64 + 16 pad)
#define WSCALE 512.0f
#define NTHREADS 256

#define A_STAGE_BYTES (BM * ROWPAD)     // 10240
#define B_STAGE_BYTES (BN * ROWPAD)     // 10240
#define SMEM_BYTES (STAGES * (A_STAGE_BYTES + B_STAGE_BYTES))   // 81920

// -------------------- device scratch (static: no allocs) -------------------
__device__ float   g_Wf[HID * HID];            // 16 MB fp32 dense W
__device__ uint8_t g_Wq[HID * HID];            // 4 MB e4m3 W*512, [i][j] j contig
__device__ uint8_t g_Xq[MROWS_MAX * HID];      // 16 MB e4m3 x_prev

// -------------------- preprocessing ----------------------------------------
__global__ void zero_w_kernel() {
    float4* p = reinterpret_cast<float4*>(g_Wf);
    for (int i = blockIdx.x * blockDim.x + threadIdx.x; i < HID * HID / 4;
         i += gridDim.x * blockDim.x)
        p[i] = make_float4(0.f, 0.f, 0.f, 0.f);
}

__global__ void scatter_kernel(const int* __restrict__ idx,
                               const float* __restrict__ val, int nnz) {
    int k = blockIdx.x * blockDim.x + threadIdx.x;
    if (k < nnz) {
        int i = idx[k];
        int j = idx[nnz + k];
        atomicAdd(&g_Wf[(size_t)i * HID + j], val[k]);
    }
}

__device__ __forceinline__ uint16_t f2_to_e4m3x2(float lo, float hi) {
    uint16_t p;
    asm("cvt.rn.satfinite.e4m3x2.f32 %0, %1, %2;" : "=h"(p) : "f"(hi), "f"(lo));
    return p;
}

// 16 fp32 in -> 16 fp8 out per thread (16B store)
__global__ void conv_w_kernel() {
    int i = blockIdx.x * blockDim.x + threadIdx.x;
    if (i < HID * HID / 16) {
        uint32_t o[4];
#pragma unroll
        for (int q = 0; q < 4; q++) {
            float4 v = reinterpret_cast<const float4*>(g_Wf)[4 * i + q];
            o[q] = (uint32_t)f2_to_e4m3x2(v.x * WSCALE, v.y * WSCALE) |
                   ((uint32_t)f2_to_e4m3x2(v.z * WSCALE, v.w * WSCALE) << 16);
        }
        reinterpret_cast<uint4*>(g_Wq)[i] = make_uint4(o[0], o[1], o[2], o[3]);
    }
}

__global__ void conv_x_kernel(const float* __restrict__ src, int n16) {
    int i = blockIdx.x * blockDim.x + threadIdx.x;
    if (i < n16) {
        uint32_t o[4];
#pragma unroll
        for (int q = 0; q < 4; q++) {
            float4 v = reinterpret_cast<const float4*>(src)[4 * i + q];
            o[q] = (uint32_t)f2_to_e4m3x2(v.x, v.y) |
                   ((uint32_t)f2_to_e4m3x2(v.z, v.w) << 16);
        }
        reinterpret_cast<uint4*>(g_Xq)[i] = make_uint4(o[0], o[1], o[2], o[3]);
    }
}

// -------------------- GEMM helpers ------------------------------------------
__device__ __forceinline__ void cp_async16(uint32_t dst, const void* src) {
    asm volatile("cp.async.cg.shared.global [%0], [%1], 16;" :: "r"(dst), "l"(src));
}
__device__ __forceinline__ void cp_commit() {
    asm volatile("cp.async.commit_group;" ::: "memory");
}
template <int N>
__device__ __forceinline__ void cp_wait() {
    asm volatile("cp.async.wait_group %0;" :: "n"(N) : "memory");
}

__device__ __forceinline__ void ldsm_x4(uint32_t& r0, uint32_t& r1, uint32_t& r2,
                                        uint32_t& r3, uint32_t addr) {
    asm volatile("ldmatrix.sync.aligned.m8n8.x4.shared.b16 {%0,%1,%2,%3}, [%4];"
                 : "=r"(r0), "=r"(r1), "=r"(r2), "=r"(r3) : "r"(addr));
}

// FP8 e4m3 MMA, K=32, F16 accumulate (packed 2xf16 per .b32).
__device__ __forceinline__ void mma_fp8_f16(uint32_t& c0, uint32_t& c1,
                                            uint32_t a0, uint32_t a1, uint32_t a2, uint32_t a3,
                                            uint32_t b0, uint32_t b1) {
    asm volatile(
        "mma.sync.aligned.m16n8k32.row.col.f16.e4m3.e4m3.f16 "
        "{%0,%1}, {%2,%3,%4,%5}, {%6,%7}, {%0,%1};"
        : "+r"(c0), "+r"(c1)
        : "r"(a0), "r"(a1), "r"(a2), "r"(a3), "r"(b0), "r"(b1));
}

// Load one K-chunk (stage): A 128x64B + B 128x64B via 16B cp.async.
// 1024 chunks over 256 threads = 4 per thread.
__device__ __forceinline__ void load_stage(uint32_t smA, uint32_t smB,
                                           int kt, int m0, int n0, int tid) {
    const int k0 = kt * BK;
#pragma unroll
    for (int i = 0; i < 4; i++) {
        int t = tid + i * NTHREADS;    // 0..1023 ; A: [0,512), B: [512,1024)
        bool isB = t >= 512;
        int u = isB ? t - 512 : t;
        int row = u >> 2;
        int c = u & 3;                 // 16B chunk within 64B row
        const uint8_t* g = isB
            ? g_Wq + (size_t)(n0 + row) * HID + k0 + c * 16
            : g_Xq + (size_t)(m0 + row) * HID + k0 + c * 16;
        uint32_t dst = (isB ? smB : smA) + (uint32_t)(row * ROWPAD + c * 16);
        cp_async16(dst, g);
    }
    cp_commit();
}

// -------------------- GEMM kernel -------------------------------------------
__global__ __launch_bounds__(NTHREADS, 2)
void gemm_kernel(const float* __restrict__ x_cur,
                 const float* __restrict__ alpha_p,
                 float* __restrict__ out) {
    extern __shared__ char smraw[];
    const int tid  = threadIdx.x;
    const int wid  = tid >> 5;
    const int lane = tid & 31;
    const int n0 = blockIdx.x * BN;
    const int m0 = blockIdx.y * BM;
    const int wm = wid & 1;            // 2 warps along M (64 rows each)
    const int wn = wid >> 1;           // 4 warps along N (32 cols each)
    const int rm = wm * 64;
    const int rn = wn * 32;

    uint32_t smem;
    asm("{ .reg .u64 t; cvta.to.shared.u64 t, %1; cvt.u32.u64 %0, t; }"
        : "=r"(smem) : "l"(smraw));
    uint32_t smA[STAGES], smB[STAGES];
#pragma unroll
    for (int s = 0; s < STAGES; s++) {
        smA[s] = smem + s * A_STAGE_BYTES;
        smB[s] = smem + STAGES * A_STAGE_BYTES + s * B_STAGE_BYTES;
    }

    // acc[mf][nf]: packed f16x2 pairs (warp tile 64m x 32n)
    uint32_t acc[4][4][2];
#pragma unroll
    for (int mf = 0; mf < 4; mf++)
#pragma unroll
        for (int nf = 0; nf < 4; nf++) {
            acc[mf][nf][0] = 0u; acc[mf][nf][1] = 0u;
        }

    load_stage(smA[0], smB[0], 0, m0, n0, tid);
    load_stage(smA[1], smB[1], 1, m0, n0, tid);
    load_stage(smA[2], smB[2], 2, m0, n0, tid);
    cp_wait<2>();
    __syncthreads();

    const int ldrowA = rm + (lane & 15);
    const int ldrowB = rn + (lane & 15);
    const int ldcol  = (lane >> 4) * 16;

    for (int kt = 0; kt < NKT; kt++) {
        const int s = kt & (STAGES - 1);
        if (kt + 3 < NKT)
            load_stage(smA[(kt + 3) & (STAGES - 1)], smB[(kt + 3) & (STAGES - 1)],
                       kt + 3, m0, n0, tid);

#pragma unroll
        for (int ks = 0; ks < 2; ks++) {     // two k32 steps in BK=64
            uint32_t a[4][4], b[2][4];
#pragma unroll
            for (int mf = 0; mf < 4; mf++) {
                uint32_t addr = smA[s] +
                    (uint32_t)((ldrowA + mf * 16) * ROWPAD + ks * 32 + ldcol);
                ldsm_x4(a[mf][0], a[mf][1], a[mf][2], a[mf][3], addr);
            }
#pragma unroll
            for (int bf = 0; bf < 2; bf++) {
                uint32_t addr = smB[s] +
                    (uint32_t)((ldrowB + bf * 16) * ROWPAD + ks * 32 + ldcol);
                ldsm_x4(b[bf][0], b[bf][1], b[bf][2], b[bf][3], addr);
            }
#pragma unroll
            for (int mf = 0; mf < 4; mf++)
#pragma unroll
                for (int bf = 0; bf < 2; bf++) {
                    mma_fp8_f16(acc[mf][2 * bf][0], acc[mf][2 * bf][1],
                                a[mf][0], a[mf][1], a[mf][2], a[mf][3],
                                b[bf][0], b[bf][2]);
                    mma_fp8_f16(acc[mf][2 * bf + 1][0], acc[mf][2 * bf + 1][1],
                                a[mf][0], a[mf][1], a[mf][2], a[mf][3],
                                b[bf][1], b[bf][3]);
                }
        }

        if (kt + 3 < NKT) cp_wait<2>(); else cp_wait<0>();
        __syncthreads();
    }

    // -------------------- fused epilogue: out = x_cur + (alpha/512)*acc ----
    const float alpha = __ldg(alpha_p) * (1.0f / WSCALE);
#pragma unroll
    for (int mf = 0; mf < 4; mf++) {
        const int r = m0 + rm + mf * 16 + (lane >> 2);
#pragma unroll
        for (int nf = 0; nf < 4; nf++) {
            const int cidx = n0 + rn + nf * 8 + (lane & 3) * 2;
            size_t g0 = (size_t)r * HID + cidx;
            float2 v0 = __half22float2(*reinterpret_cast<__half2*>(&acc[mf][nf][0]));
            float2 x0 = *reinterpret_cast<const float2*>(x_cur + g0);
            float2 o0;
            o0.x = fmaf(alpha, v0.x, x0.x);
            o0.y = fmaf(alpha, v0.y, x0.y);
            *reinterpret_cast<float2*>(out + g0) = o0;
            size_t g1 = g0 + (size_t)8 * HID;
            float2 v1 = __half22float2(*reinterpret_cast<__half2*>(&acc[mf][nf][1]));
            float2 x1 = *reinterpret_cast<const float2*>(x_cur + g1);
            float2 o1;
            o1.x = fmaf(alpha, v1.x, x1.x);
            o1.y = fmaf(alpha, v1.y, x1.y);
            *reinterpret_cast<float2*>(out + g1) = o1;
        }
    }
}

// -------------------- launcher ---------------------------------------------
extern "C" void kernel_launch(void* const* d_in, const int* in_sizes, int n_in,
                              void* d_out, int out_size) {
    const float* x_cur  = (const float*)d_in[0];
    const float* x_prev = (const float*)d_in[1];
    const float* alpha  = (const float*)d_in[2];
    const float* vals   = (const float*)d_in[3];
    const int*   idx    = (const int*)d_in[4];
    const int nnz   = in_sizes[3];
    const int mrows = in_sizes[0] / HID;     // 8192

    cudaFuncSetAttribute(gemm_kernel,
                         cudaFuncAttributeMaxDynamicSharedMemorySize, SMEM_BYTES);

    zero_w_kernel<<<2048, 256>>>();
    scatter_kernel<<<(nnz + 255) / 256, 256>>>(idx, vals, nnz);
    conv_w_kernel<<<(HID * HID / 16 + 255) / 256, 256>>>();
    const int n16x = mrows * HID / 16;
    conv_x_kernel<<<(n16x + 255) / 256, 256>>>(x_prev, n16x);

    dim3 grid(HID / BN, mrows / BM);         // 16 x 64 = 1024 CTAs
    gemm_kernel<<<grid, NTHREADS, SMEM_BYTES>>>(x_cur, alpha, (float*)d_out);
}